// round 2
// baseline (speedup 1.0000x reference)
#include <cuda_runtime.h>

// NCN recurrence, fully decomposed by (batch, head).
//
// Key facts exploited:
//  * step t only depends on step t-8 (cache slot t % 8)  -> 8 parallel chains per (b,h)
//  * heads never mix; module m+1's inputs for (b,h) come only from module m's (b,h)
//    -> one persistent block per (b,h) runs all 4 modules, cache stays in registers
//  * alpha = 0.5 folded into the tanh exponent (tanh(u/2) = 1 - 2/(e^u + 1))
//  * weights live in registers as f32x2 k-pairs; mat-vec via fma.rn.f32x2 (2 FLOP/instr)
//  * modules 1 and 2 run IN PLACE on the scratch buffer: position p is read at
//    iteration p-3 (prefetch depth 3) and written at iteration p, so no overlap.

#define NB 8
#define NT 4096
#define ND 1024
#define NH 16
#define DH 64
#define NC 8
#define NSTEPS (NT / NC)   // 512
#define NMOD 4
#define BTD (NB * NT * ND) // 33554432

// Inter-module activation scratch (modules 0->1->2->3 flow through this in place).
__device__ float g_buf[BTD];

typedef unsigned long long u64;

__device__ __forceinline__ u64 ffma2(u64 a, u64 b, u64 c) {
    u64 d;
    asm("fma.rn.f32x2 %0, %1, %2, %3;" : "=l"(d) : "l"(a), "l"(b), "l"(c));
    return d;
}
__device__ __forceinline__ u64 fadd2(u64 a, u64 b) {
    u64 d;
    asm("add.rn.f32x2 %0, %1, %2;" : "=l"(d) : "l"(a), "l"(b));
    return d;
}
__device__ __forceinline__ u64 packf2(float lo, float hi) {
    u64 d;
    asm("mov.b64 %0, {%1, %2};" : "=l"(d) : "f"(lo), "f"(hi));
    return d;
}
__device__ __forceinline__ float2 unpackf2(u64 v) {
    float lo, hi;
    asm("mov.b64 {%0, %1}, %2;" : "=f"(lo), "=f"(hi) : "l"(v));
    return make_float2(lo, hi);
}

// tanh(0.5f * u), accurate to ~1e-6 abs (ex2/rcp approx are ~2^-22 rel).
// tanh(u/2) = 1 - 2 / (e^u + 1),  e^u = 2^(u * log2(e))
__device__ __forceinline__ float tanh_half(float u) {
    float e;
    asm("ex2.approx.f32 %0, %1;" : "=f"(e) : "f"(u * 1.4426950408889634f));
    float r;
    asm("rcp.approx.f32 %0, %1;" : "=f"(r) : "f"(e + 1.0f));
    return fmaf(-2.0f, r, 1.0f);
}

__global__ void __launch_bounds__(256, 1)
ncn_kernel(const float* __restrict__ x_in,
           const float* __restrict__ xa_in,
           const float* __restrict__ w_in,
           float* __restrict__ out_x,
           float* __restrict__ out_xa)
{
    __shared__ float shW[DH * DH];      // 16 KB weight staging
    __shared__ float shx[8][3][DH];     // 6 KB: per-warp 3-deep x ring

    const int b    = blockIdx.x >> 4;   // grid = 128 = B * H
    const int h    = blockIdx.x & 15;
    const int warp = threadIdx.x >> 5;  // warp == cache slot s
    const int lane = threadIdx.x & 31;
    const int s    = warp;
    const int e0   = lane * 2;          // this thread's two output channels e0, e0+1

    // Cache value for (b, slot s, head h, channels e0..e0+1). Lives in registers
    // across all 4 modules (module m+1's initial cache == module m's final cache).
    float2 c2 = *(const float2*)(xa_in + ((size_t)(b * NC + s) * ND + h * DH + e0));

    // Per-thread weights: w0[kp] = (W[2kp][e0],   W[2kp+1][e0])
    //                     w1[kp] = (W[2kp][e0+1], W[2kp+1][e0+1])
    u64 w0[32], w1[32];

    #pragma unroll 1
    for (int m = 0; m < NMOD; ++m) {
        const float* src = (m == 0) ? x_in : g_buf;
        float*       dst = (m == NMOD - 1) ? out_x : g_buf;

        // Load W[m][h] (64x64) into shared, then gather this thread's k-pair columns.
        __syncthreads();  // protect shW against warps still gathering previous module
        const float* wg = w_in + (size_t)(m * NH + h) * DH * DH;
        for (int i = threadIdx.x; i < DH * DH; i += 256) shW[i] = wg[i];
        __syncthreads();
        #pragma unroll
        for (int kp = 0; kp < 32; ++kp) {
            w0[kp] = packf2(shW[(2 * kp) * DH + e0],     shW[(2 * kp + 1) * DH + e0]);
            w1[kp] = packf2(shW[(2 * kp) * DH + e0 + 1], shW[(2 * kp + 1) * DH + e0 + 1]);
        }

        const float* xp = src + (size_t)b * NT * ND + (size_t)s * ND + h * DH + e0;
        float*       yp = dst + (size_t)b * NT * ND + (size_t)s * ND + h * DH + e0;
        const size_t stride = (size_t)NC * ND;  // 8 tokens ahead = same slot, next step

        // ---- prime the x pipeline (depth-2 LDG prefetch + 3-buffer smem ring) ----
        float2 r0  = *(const float2*)(xp);                 // x(step 0)
        float2 pxa = *(const float2*)(xp + stride);        // x(step 1)
        float2 pxb = *(const float2*)(xp + 2 * stride);    // x(step 2)
        *(float2*)&shx[warp][0][e0] = r0;
        __syncwarp();

        int bread = 0, bwrite = 1;
        #pragma unroll 1
        for (int p = 0; p < NSTEPS; ++p) {
            // stage x(p+1) into the ring; refill prefetch regs with x(p+3)
            *(float2*)&shx[warp][bwrite][e0] = pxa;
            pxa = pxb;
            if (p + 3 < NSTEPS)
                pxb = *(const float2*)(xp + (size_t)(p + 3) * stride);
            __syncwarp();  // orders this STS before next iteration's LDS of that buffer

            // mat-vec: mix[e] = sum_k x[k] * W[k][e], packed over k-pairs
            const ulonglong2* xs = (const ulonglong2*)&shx[warp][bread][0];
            u64 a00 = 0, a01 = 0, a10 = 0, a11 = 0;
            #pragma unroll
            for (int i = 0; i < 16; ++i) {
                ulonglong2 xv = xs[i];   // LDS.128 broadcast: (x[4i],x[4i+1]),(x[4i+2],x[4i+3])
                a00 = ffma2(xv.x, w0[2 * i],     a00);
                a10 = ffma2(xv.x, w1[2 * i],     a10);
                a01 = ffma2(xv.y, w0[2 * i + 1], a01);
                a11 = ffma2(xv.y, w1[2 * i + 1], a11);
            }
            float2 m0 = unpackf2(fadd2(a00, a01));
            float2 m1 = unpackf2(fadd2(a10, a11));
            float mix0 = m0.x + m0.y;
            float mix1 = m1.x + m1.y;

            // y = tanh(alpha*c + (1-alpha)*mix), alpha = 0.5 -> tanh(0.5*(c+mix))
            c2.x = tanh_half(c2.x + mix0);
            c2.y = tanh_half(c2.y + mix1);

            *(float2*)(yp + (size_t)p * stride) = c2;

            bread  = bwrite;
            bwrite = bwrite + 1;
            if (bwrite == 3) bwrite = 0;
        }
    }

    // Final cache = xa output (slot s final value == y at token T-8+s, already in c2)
    *(float2*)(out_xa + (size_t)(b * NC + s) * ND + h * DH + e0) = c2;
}

extern "C" void kernel_launch(void* const* d_in, const int* in_sizes, int n_in,
                              void* d_out, int out_size) {
    const float* x  = (const float*)d_in[0];   // [8, 4096, 1024] fp32
    const float* xa = (const float*)d_in[1];   // [8, 8, 1024]    fp32
    const float* w  = (const float*)d_in[2];   // [4, 16, 64, 64] fp32

    float* out_x  = (float*)d_out;                         // x part: BTD elements
    float* out_xa = (float*)d_out + (out_size - NB * NC * ND);  // xa part: last 65536

    ncn_kernel<<<NB * NH, 256>>>(x, xa, w, out_x, out_xa);
}

// round 4
// speedup vs baseline: 1.0569x; 1.0569x over previous
#include <cuda_runtime.h>

// NCN recurrence, decomposed by (batch, head); one channel per thread so the
// per-thread weight stash is 32 x u64 = 64 regs (the 2-ch/thread variant
// spilled: regs=190, L1=25% local traffic, 1110us).
//
//  * step t depends only on step t-8  -> 8 independent slot chains per (b,h)
//  * heads never mix across modules   -> one persistent block per (b,h),
//    cache slot values live in registers across all 4 modules
//  * warp = (slot, channel-half): 16 warps/block, each warp self-contained
//    (stages its own copy of the 64 x-channels -> no cross-warp sync)
//  * weights as f32x2 k-pairs in registers; mat-vec via fma.rn.f32x2
//  * tanh(u/2) = 1 - 2/(e^u + 1) via ex2.approx + rcp.approx
//  * ping-pong buffers = one 128MB static + the x-section of d_out
//    (>=256MB of __device__ statics correlates with container failures;
//    d_out is writable scratch until kernel_launch returns)

#define NB 8
#define NT 4096
#define ND 1024
#define NH 16
#define DH 64
#define NC 8
#define NSTEPS (NT / NC)   // 512
#define NMOD 4
#define BTD (NB * NT * ND) // 33554432

// Single inter-module scratch buffer (128 MB). The second ping-pong buffer is
// the x-section of d_out. Chain: x_in -> g_buf -> out_x -> g_buf -> out_x.
__device__ float g_buf[BTD];

typedef unsigned long long u64;

__device__ __forceinline__ u64 ffma2(u64 a, u64 b, u64 c) {
    u64 d;
    asm("fma.rn.f32x2 %0, %1, %2, %3;" : "=l"(d) : "l"(a), "l"(b), "l"(c));
    return d;
}
__device__ __forceinline__ u64 fadd2(u64 a, u64 b) {
    u64 d;
    asm("add.rn.f32x2 %0, %1, %2;" : "=l"(d) : "l"(a), "l"(b));
    return d;
}
__device__ __forceinline__ u64 packf2(float lo, float hi) {
    u64 d;
    asm("mov.b64 %0, {%1, %2};" : "=l"(d) : "f"(lo), "f"(hi));
    return d;
}
__device__ __forceinline__ float2 unpackf2(u64 v) {
    float lo, hi;
    asm("mov.b64 {%0, %1}, %2;" : "=f"(lo), "=f"(hi) : "l"(v));
    return make_float2(lo, hi);
}

// tanh(0.5f * u) = 1 - 2/(e^u + 1); ex2/rcp approx, ~1e-6 abs error.
__device__ __forceinline__ float tanh_half(float u) {
    float e;
    asm("ex2.approx.f32 %0, %1;" : "=f"(e) : "f"(u * 1.4426950408889634f));
    float r;
    asm("rcp.approx.f32 %0, %1;" : "=f"(r) : "f"(e + 1.0f));
    return fmaf(-2.0f, r, 1.0f);
}

__global__ void __launch_bounds__(512, 1)
ncn_kernel(const float* __restrict__ x_in,
           const float* __restrict__ xa_in,
           const float* __restrict__ w_in,
           float* __restrict__ out_x,
           float* __restrict__ out_xa)
{
    __shared__ float shW[DH * DH];        // 16 KB weight staging
    __shared__ float shx[16][3][DH];      // 12 KB: per-warp 3-deep x ring

    const int b    = blockIdx.x >> 4;     // grid = 128 = B * H
    const int h    = blockIdx.x & 15;
    const int warp = threadIdx.x >> 5;
    const int lane = threadIdx.x & 31;
    const int s    = warp & 7;            // cache slot
    const int half = warp >> 3;           // channel half
    const int e    = half * 32 + lane;    // this thread's single output channel

    // Cache value for (b, slot s, head h, channel e); persists across modules.
    float c = xa_in[(size_t)(b * NC + s) * ND + h * DH + e];

    // Per-thread weights: w[kp] = (W[2kp][e], W[2kp+1][e])  -> 32 u64 = 64 regs
    u64 w[32];

    #pragma unroll 1
    for (int m = 0; m < NMOD; ++m) {
        // Ping-pong: x_in -> g_buf -> out_x -> g_buf -> out_x
        const float* src = (m == 0) ? x_in  : (m & 1) ? g_buf : out_x;
        float*       dst = (m & 1) ? out_x : g_buf;

        // Stage W[m][h] (64x64) to shared, gather this thread's column as k-pairs.
        __syncthreads();
        const float* wg = w_in + (size_t)(m * NH + h) * DH * DH;
        for (int i = threadIdx.x; i < DH * DH; i += 512) shW[i] = wg[i];
        __syncthreads();
        #pragma unroll
        for (int kp = 0; kp < 32; ++kp)
            w[kp] = packf2(shW[(2 * kp) * DH + e], shW[(2 * kp + 1) * DH + e]);

        // x pointer for staging (this lane loads channels 2*lane, 2*lane+1),
        // y pointer for this thread's output channel.
        const size_t base = (size_t)b * NT * ND + (size_t)s * ND + h * DH;
        const float* xp = src + base + 2 * lane;
        float*       yp = dst + base + e;
        const size_t stride = (size_t)NC * ND;  // next step of this slot chain

        // Prime: depth-2 LDG prefetch + 3-buffer smem ring (per warp).
        float2 r0  = *(const float2*)(xp);
        float2 pxa = *(const float2*)(xp + stride);
        float2 pxb = *(const float2*)(xp + 2 * stride);
        const float* xpf = xp + 3 * stride;     // prefetch cursor (step p+3)
        *(float2*)&shx[warp][0][2 * lane] = r0;
        __syncwarp();

        int bread = 0, bwrite = 1;
        #pragma unroll 1
        for (int p = 0; p < NSTEPS; ++p) {
            // stage x(p+1); refill prefetch regs with x(p+3)
            *(float2*)&shx[warp][bwrite][2 * lane] = pxa;
            pxa = pxb;
            if (p + 3 < NSTEPS) pxb = *(const float2*)(xpf);
            xpf += stride;
            __syncwarp();

            // mix[e] = sum_k x[k] * W[k][e]; x is warp-uniform (LDS broadcast)
            const ulonglong2* xs = (const ulonglong2*)&shx[warp][bread][0];
            u64 a0 = 0, a1 = 0;
            #pragma unroll
            for (int i = 0; i < 16; ++i) {
                ulonglong2 xv = xs[i];            // (x[4i],x[4i+1]), (x[4i+2],x[4i+3])
                a0 = ffma2(xv.x, w[2 * i],     a0);
                a1 = ffma2(xv.y, w[2 * i + 1], a1);
            }
            float2 mm = unpackf2(fadd2(a0, a1));
            float mix = mm.x + mm.y;

            // y = tanh(0.5*(c + mix)); becomes the new cache value for this slot
            c = tanh_half(c + mix);
            yp[(size_t)p * stride] = c;

            bread  = bwrite;
            bwrite = bwrite + 1;
            if (bwrite == 3) bwrite = 0;
        }
    }

    // Final cache for slot s == its last written y value (still in c).
    out_xa[(size_t)(b * NC + s) * ND + h * DH + e] = c;
}

extern "C" void kernel_launch(void* const* d_in, const int* in_sizes, int n_in,
                              void* d_out, int out_size) {
    const float* x  = (const float*)d_in[0];   // [8, 4096, 1024] fp32
    const float* xa = (const float*)d_in[1];   // [8, 8, 1024]    fp32
    const float* w  = (const float*)d_in[2];   // [4, 16, 64, 64] fp32

    float* out_x  = (float*)d_out;                              // x part
    float* out_xa = (float*)d_out + (out_size - NB * NC * ND);  // xa part (last 65536)

    ncn_kernel<<<NB * NH, 512>>>(x, xa, w, out_x, out_xa);
}

// round 5
// speedup vs baseline: 1.1345x; 1.0734x over previous
#include <cuda_runtime.h>

// NCN recurrence, decomposed by (batch, head).
// R4 diagnosis: per-iteration __syncwarp + unroll-1 loop serialized each step
// (exposed LDS + MUFU latency, issue=35%). This version:
//  * k-split: lanes 0-15 take k[0:32), lanes 16-31 take k[32:64); lane pair
//    (l, l^16) covers 2 channels; combine via shfl.bfly(16). Weights still 64
//    regs/thread; per-step LDS halves to 8 instrs of 16 u64 (32 regs).
//  * 2-step groups over a 4-deep smem ring: one syncwarp per 2 steps, and no
//    barrier between the 2 steps' LDS+compute -> ptxas overlaps across steps.
//  * tanh(u/2) = 1 - 2/(e^u+1) via ex2.approx + rcp.approx.
//  * ping-pong buffers: one 128MB __device__ static + the x-section of d_out
//    (>=256MB static correlated with container failures).

#define NB 8
#define NT 4096
#define ND 1024
#define NH 16
#define DH 64
#define NC 8
#define NSTEPS (NT / NC)   // 512
#define NMOD 4
#define BTD (NB * NT * ND) // 33554432

__device__ float g_buf[BTD];

typedef unsigned long long u64;

__device__ __forceinline__ u64 ffma2(u64 a, u64 b, u64 c) {
    u64 d;
    asm("fma.rn.f32x2 %0, %1, %2, %3;" : "=l"(d) : "l"(a), "l"(b), "l"(c));
    return d;
}
__device__ __forceinline__ u64 fadd2(u64 a, u64 b) {
    u64 d;
    asm("add.rn.f32x2 %0, %1, %2;" : "=l"(d) : "l"(a), "l"(b));
    return d;
}
__device__ __forceinline__ u64 packf2(float lo, float hi) {
    u64 d;
    asm("mov.b64 %0, {%1, %2};" : "=l"(d) : "f"(lo), "f"(hi));
    return d;
}
__device__ __forceinline__ float2 unpackf2(u64 v) {
    float lo, hi;
    asm("mov.b64 {%0, %1}, %2;" : "=f"(lo), "=f"(hi) : "l"(v));
    return make_float2(lo, hi);
}
__device__ __forceinline__ u64 shflx16_u64(u64 v) {
    float2 f = unpackf2(v);
    float a, b;
    asm("shfl.sync.bfly.b32 %0, %1, 16, 0x1F, 0xFFFFFFFF;" : "=f"(a) : "f"(f.x));
    asm("shfl.sync.bfly.b32 %0, %1, 16, 0x1F, 0xFFFFFFFF;" : "=f"(b) : "f"(f.y));
    return packf2(a, b);
}

// tanh(0.5f*u) = 1 - 2/(e^u + 1); ~1e-6 abs error.
__device__ __forceinline__ float tanh_half(float u) {
    float e;
    asm("ex2.approx.f32 %0, %1;" : "=f"(e) : "f"(u * 1.4426950408889634f));
    float r;
    asm("rcp.approx.f32 %0, %1;" : "=f"(r) : "f"(e + 1.0f));
    return fmaf(-2.0f, r, 1.0f);
}

struct Step { float2 c; };

__global__ void __launch_bounds__(512, 1)
ncn_kernel(const float* __restrict__ x_in,
           const float* __restrict__ xa_in,
           const float* __restrict__ w_in,
           float* __restrict__ out_x,
           float* __restrict__ out_xa)
{
    __shared__ float shW[DH * DH];        // 16 KB weight staging
    __shared__ float shx[16][4][DH];      // 16 KB: per-warp 4-deep x ring

    const int b    = blockIdx.x >> 4;     // grid = 128 = B * H
    const int h    = blockIdx.x & 15;
    const int warp = threadIdx.x >> 5;
    const int lane = threadIdx.x & 31;
    const int s    = warp & 7;            // cache slot (= this warp's chain)
    const int hf   = warp >> 3;           // channel half (0: ch 0-31, 1: ch 32-63)
    const int kl   = lane >> 4;           // k-split: 0 -> k[0:32), 1 -> k[32:64)
    const int j    = lane & 15;
    const int e0   = hf * 32 + 2 * j;     // this lane-pair's channels e0, e0+1

    // Cache value (channels e0,e0+1 of slot s); both kl-partners hold a copy.
    float2 c2 = *(const float2*)(xa_in + (size_t)(b * NC + s) * ND + h * DH + e0);

    // Weights for this lane's k-range and 2 channels: 32 u64 = 64 regs.
    // wA[i] = (W[2kp][e0],   W[2kp+1][e0]),   kp = kl*16 + i
    // wB[i] = (W[2kp][e0+1], W[2kp+1][e0+1])
    u64 wA[16], wB[16];

    #pragma unroll 1
    for (int m = 0; m < NMOD; ++m) {
        // Ping-pong: x_in -> g_buf -> out_x -> g_buf -> out_x
        const float* src = (m == 0) ? x_in  : (m & 1) ? g_buf : out_x;
        float*       dst = (m & 1) ? out_x : g_buf;

        __syncthreads();
        const float* wg = w_in + (size_t)(m * NH + h) * DH * DH;
        for (int i = threadIdx.x; i < DH * DH; i += 512) shW[i] = wg[i];
        __syncthreads();
        #pragma unroll
        for (int i = 0; i < 16; ++i) {
            int k0 = (kl * 16 + i) * 2;
            wA[i] = packf2(shW[k0 * DH + e0],     shW[(k0 + 1) * DH + e0]);
            wB[i] = packf2(shW[k0 * DH + e0 + 1], shW[(k0 + 1) * DH + e0 + 1]);
        }

        const size_t base   = (size_t)b * NT * ND + (size_t)s * ND + h * DH;
        const size_t stride = (size_t)NC * ND;     // next step of this slot chain
        const float* xp = src + base + 2 * lane;   // staging: lane loads ch 2l,2l+1
        float*       yp = dst + base + e0;         // output (kl==0 lanes write)

        // ---- prime: stage x(0..3) into ring, prefetch x(4),x(5) into regs ----
        {
            float2 r0 = *(const float2*)(xp);
            float2 r1 = *(const float2*)(xp + stride);
            float2 r2 = *(const float2*)(xp + 2 * stride);
            float2 r3 = *(const float2*)(xp + 3 * stride);
            *(float2*)&shx[warp][0][2 * lane] = r0;
            *(float2*)&shx[warp][1][2 * lane] = r1;
            *(float2*)&shx[warp][2][2 * lane] = r2;
            *(float2*)&shx[warp][3][2 * lane] = r3;
        }
        float2 pxa = *(const float2*)(xp + 4 * stride);
        float2 pxb = *(const float2*)(xp + 5 * stride);
        const float* xpf = xp + 6 * stride;   // LDG cursor: x(p+6) at group p

        // ---- main loop: groups of 2 steps (p, p+1), p even ----
        #pragma unroll 1
        for (int p = 0; p < NSTEPS; p += 2) {
            const int pair = (p >> 1) & 1;    // ring buffer pair: {0,1} or {2,3}
            float* bufA = &shx[warp][2 * pair][0];
            float* bufB = &shx[warp][2 * pair + 1][0];

            __syncwarp();   // prior STS into these buffers is visible

            // Loads for both steps (no barrier between them and compute ->
            // ptxas overlaps LDS(step p+1) with compute(step p)).
            const ulonglong2* xsA = (const ulonglong2*)(bufA + kl * 32);
            const ulonglong2* xsB = (const ulonglong2*)(bufB + kl * 32);

            // ---- step p ----
            {
                u64 a0 = 0, a1 = 0;
                #pragma unroll
                for (int i = 0; i < 8; ++i) {
                    ulonglong2 xv = xsA[i];
                    a0 = ffma2(xv.x, wA[2 * i],     a0);
                    a1 = ffma2(xv.x, wB[2 * i],     a1);
                    a0 = ffma2(xv.y, wA[2 * i + 1], a0);
                    a1 = ffma2(xv.y, wB[2 * i + 1], a1);
                }
                a0 = fadd2(a0, shflx16_u64(a0));   // combine k-halves
                a1 = fadd2(a1, shflx16_u64(a1));
                float2 f0 = unpackf2(a0), f1 = unpackf2(a1);
                c2.x = tanh_half(c2.x + f0.x + f0.y);
                c2.y = tanh_half(c2.y + f1.x + f1.y);
                if (kl == 0) *(float2*)(yp + (size_t)p * stride) = c2;
            }
            // ---- step p+1 ----
            {
                u64 a0 = 0, a1 = 0;
                #pragma unroll
                for (int i = 0; i < 8; ++i) {
                    ulonglong2 xv = xsB[i];
                    a0 = ffma2(xv.x, wA[2 * i],     a0);
                    a1 = ffma2(xv.x, wB[2 * i],     a1);
                    a0 = ffma2(xv.y, wA[2 * i + 1], a0);
                    a1 = ffma2(xv.y, wB[2 * i + 1], a1);
                }
                a0 = fadd2(a0, shflx16_u64(a0));
                a1 = fadd2(a1, shflx16_u64(a1));
                float2 f0 = unpackf2(a0), f1 = unpackf2(a1);
                c2.x = tanh_half(c2.x + f0.x + f0.y);
                c2.y = tanh_half(c2.y + f1.x + f1.y);
                if (kl == 0) *(float2*)(yp + (size_t)(p + 1) * stride) = c2;
            }

            __syncwarp();   // all reads of bufA/bufB done before rewrite

            // Stage x(p+4), x(p+5) into the buffers just freed.
            *(float2*)(bufA + 2 * lane) = pxa;
            *(float2*)(bufB + 2 * lane) = pxb;

            // Refill prefetch regs with x(p+6), x(p+7).
            if (p + 6 < NSTEPS) pxa = *(const float2*)(xpf);
            if (p + 7 < NSTEPS) pxb = *(const float2*)(xpf + stride);
            xpf += 2 * stride;
        }
    }

    // Final cache for slot s == its last y value (in c2); kl==0 lanes write.
    if (kl == 0)
        *(float2*)(out_xa + (size_t)(b * NC + s) * ND + h * DH + e0) = c2;
}

extern "C" void kernel_launch(void* const* d_in, const int* in_sizes, int n_in,
                              void* d_out, int out_size) {
    const float* x  = (const float*)d_in[0];   // [8, 4096, 1024] fp32
    const float* xa = (const float*)d_in[1];   // [8, 8, 1024]    fp32
    const float* w  = (const float*)d_in[2];   // [4, 16, 64, 64] fp32

    float* out_x  = (float*)d_out;                              // x part
    float* out_xa = (float*)d_out + (out_size - NB * NC * ND);  // xa part (last 65536)

    ncn_kernel<<<NB * NH, 512>>>(x, xa, w, out_x, out_xa);
}

// round 7
// speedup vs baseline: 1.6728x; 1.4745x over previous
#include <cuda_runtime.h>

// NCN recurrence, decomposed by (batch, head).  [Resubmission of the R6 kernel:
// that round died to a container-acquisition flake, not a kernel property --
// the R5 kernel with the identical memory footprint passed.]
//
// R5 diagnosis: alu pipe (43%) ~= fma (39.5%) -- the k-split's shfl/pack/unpack
// overhead. This version reverts to 1 channel/thread with full-k (no shfl, no
// packs beyond the accumulator combine) and deepens step-grouping:
//  * 4-step groups over an 8-deep per-warp smem ring, ONE __syncwarp per 4
//    steps (reads hit bufs p..p+3, STS hits disjoint bufs p+4..p+7; the only
//    cross-lane hazard is fenced by the group-top syncwarp).
//  * weights as f32x2 k-pairs: 32 x u64 = 64 regs/thread, no spill.
//  * 4 accumulators (short FMA chains); cache c NOT folded into the
//    accumulators so step q+1's matvec is independent of step q's tanh.
//  * tanh(u/2) = 1 - 2/(e^u+1) via ex2.approx + rcp.approx.
//  * ping-pong: one 128MB __device__ static + the x-section of d_out.

#define NB 8
#define NT 4096
#define ND 1024
#define NH 16
#define DH 64
#define NC 8
#define NSTEPS (NT / NC)   // 512
#define NMOD 4
#define BTD (NB * NT * ND) // 33554432

__device__ float g_buf[BTD];

typedef unsigned long long u64;

__device__ __forceinline__ u64 ffma2(u64 a, u64 b, u64 c) {
    u64 d;
    asm("fma.rn.f32x2 %0, %1, %2, %3;" : "=l"(d) : "l"(a), "l"(b), "l"(c));
    return d;
}
__device__ __forceinline__ u64 fadd2(u64 a, u64 b) {
    u64 d;
    asm("add.rn.f32x2 %0, %1, %2;" : "=l"(d) : "l"(a), "l"(b));
    return d;
}
__device__ __forceinline__ u64 packf2(float lo, float hi) {
    u64 d;
    asm("mov.b64 %0, {%1, %2};" : "=l"(d) : "f"(lo), "f"(hi));
    return d;
}
__device__ __forceinline__ float2 unpackf2(u64 v) {
    float lo, hi;
    asm("mov.b64 {%0, %1}, %2;" : "=f"(lo), "=f"(hi) : "l"(v));
    return make_float2(lo, hi);
}

// tanh(0.5f*u) = 1 - 2/(e^u + 1); ~1e-6 abs error.
__device__ __forceinline__ float tanh_half(float u) {
    float e;
    asm("ex2.approx.f32 %0, %1;" : "=f"(e) : "f"(u * 1.4426950408889634f));
    float r;
    asm("rcp.approx.f32 %0, %1;" : "=f"(r) : "f"(e + 1.0f));
    return fmaf(-2.0f, r, 1.0f);
}

__global__ void __launch_bounds__(512, 1)
ncn_kernel(const float* __restrict__ x_in,
           const float* __restrict__ xa_in,
           const float* __restrict__ w_in,
           float* __restrict__ out_x,
           float* __restrict__ out_xa)
{
    __shared__ float shW[DH * DH];        // 16 KB weight staging
    __shared__ float shx[16][8][DH];      // 32 KB: per-warp 8-deep x ring

    const int b    = blockIdx.x >> 4;     // grid = 128 = B * H
    const int h    = blockIdx.x & 15;
    const int warp = threadIdx.x >> 5;
    const int lane = threadIdx.x & 31;
    const int s    = warp & 7;            // cache slot (this warp's chain)
    const int hf   = warp >> 3;           // channel half
    const int e    = hf * 32 + lane;      // this thread's single output channel

    // Cache value for (b, slot s, head h, channel e); persists across modules.
    float c = xa_in[(size_t)(b * NC + s) * ND + h * DH + e];

    // Per-thread weights: w[kp] = (W[2kp][e], W[2kp+1][e]) -> 32 u64 = 64 regs.
    u64 w[32];

    #pragma unroll 1
    for (int m = 0; m < NMOD; ++m) {
        // Ping-pong: x_in -> g_buf -> out_x -> g_buf -> out_x
        const float* src = (m == 0) ? x_in  : (m & 1) ? g_buf : out_x;
        float*       dst = (m & 1) ? out_x : g_buf;

        __syncthreads();
        const float* wg = w_in + (size_t)(m * NH + h) * DH * DH;
        for (int i = threadIdx.x; i < DH * DH; i += 512) shW[i] = wg[i];
        __syncthreads();
        #pragma unroll
        for (int kp = 0; kp < 32; ++kp)
            w[kp] = packf2(shW[(2 * kp) * DH + e], shW[(2 * kp + 1) * DH + e]);

        const size_t base   = (size_t)b * NT * ND + (size_t)s * ND + h * DH;
        const size_t stride = (size_t)NC * ND;     // next step of this slot chain
        const float* xp  = src + base + 2 * lane;  // staging: lane loads ch 2l,2l+1
        float*       ypc = dst + base + e;         // output cursor

        // ---- prime: stage x(0..3) into bufs 0..3, prefetch x(4..7) ----
        {
            float2 r0 = *(const float2*)(xp);
            float2 r1 = *(const float2*)(xp + stride);
            float2 r2 = *(const float2*)(xp + 2 * stride);
            float2 r3 = *(const float2*)(xp + 3 * stride);
            *(float2*)&shx[warp][0][2 * lane] = r0;
            *(float2*)&shx[warp][1][2 * lane] = r1;
            *(float2*)&shx[warp][2][2 * lane] = r2;
            *(float2*)&shx[warp][3][2 * lane] = r3;
        }
        float2 px0 = *(const float2*)(xp + 4 * stride);
        float2 px1 = *(const float2*)(xp + 5 * stride);
        float2 px2 = *(const float2*)(xp + 6 * stride);
        float2 px3 = *(const float2*)(xp + 7 * stride);
        const float* xpf = xp + 8 * stride;   // LDG cursor: x(p+8) at group p

        // ---- main loop: groups of 4 steps ----
        #pragma unroll 1
        for (int p = 0; p < NSTEPS; p += 4) {
            const int g = (p >> 2) & 1;
            const float* rb = &shx[warp][4 * g][0];        // read bufs (x p..p+3)
            float*       wb = &shx[warp][4 * (1 - g)][0];  // write bufs

            __syncwarp();   // prior group's reads of wb done; prior STS visible

            #pragma unroll
            for (int q = 0; q < 4; ++q) {
                const ulonglong2* xs = (const ulonglong2*)(rb + q * DH);
                u64 a0 = 0, a1 = 0, a2 = 0, a3 = 0;
                #pragma unroll
                for (int i = 0; i < 8; ++i) {
                    ulonglong2 xv = xs[2 * i];
                    ulonglong2 xw = xs[2 * i + 1];
                    a0 = ffma2(xv.x, w[4 * i],     a0);
                    a1 = ffma2(xv.y, w[4 * i + 1], a1);
                    a2 = ffma2(xw.x, w[4 * i + 2], a2);
                    a3 = ffma2(xw.y, w[4 * i + 3], a3);
                }
                float2 f = unpackf2(fadd2(fadd2(a0, a1), fadd2(a2, a3)));
                // serial part: only this depends on the previous step's c
                c = tanh_half(c + f.x + f.y);
                ypc[(size_t)q * stride] = c;
            }
            ypc += 4 * stride;

            // stage x(p+4..p+7) into the other 4 buffers
            *(float2*)(wb + 0 * DH + 2 * lane) = px0;
            *(float2*)(wb + 1 * DH + 2 * lane) = px1;
            *(float2*)(wb + 2 * DH + 2 * lane) = px2;
            *(float2*)(wb + 3 * DH + 2 * lane) = px3;

            // refill prefetch regs with x(p+8..p+11)
            if (p + 8 < NSTEPS) {
                px0 = *(const float2*)(xpf);
                px1 = *(const float2*)(xpf + stride);
                px2 = *(const float2*)(xpf + 2 * stride);
                px3 = *(const float2*)(xpf + 3 * stride);
            }
            xpf += 4 * stride;
        }
    }

    // Final cache for slot s == its last y value (still in c).
    out_xa[(size_t)(b * NC + s) * ND + h * DH + e] = c;
}

extern "C" void kernel_launch(void* const* d_in, const int* in_sizes, int n_in,
                              void* d_out, int out_size) {
    const float* x  = (const float*)d_in[0];   // [8, 4096, 1024] fp32
    const float* xa = (const float*)d_in[1];   // [8, 8, 1024]    fp32
    const float* w  = (const float*)d_in[2];   // [4, 16, 64, 64] fp32

    float* out_x  = (float*)d_out;                              // x part
    float* out_xa = (float*)d_out + (out_size - NB * NC * ND);  // xa part (last 65536)

    ncn_kernel<<<NB * NH, 512>>>(x, xa, w, out_x, out_xa);
}